// round 8
// baseline (speedup 1.0000x reference)
#include <cuda_runtime.h>
#include <math.h>
#include <string.h>

#define BB 4
#define SS 2048
#define VV 64
#define DD 1024
#define PP 8
#define HH 42
#define KK 49152
#define EPSF 1e-12f
#define COSEPS 1e-8f
#define SQRT_S 45.254834f   // sqrt(2048)
#define NSC 64              // s-chunks in kavp (32 s each)

typedef unsigned long long ull;

// ---------------- scratch (static device globals; no allocs allowed) ----------------
__device__ float g_w1t[HH * DD];              // w1 transposed [H][D]
__device__ float g_n[PP * BB * SS];           // n values
__device__ float g_wsm[PP * BB * SS];         // softmax weights over s
__device__ float g_avp[PP * BB * NSC * DD];   // a_v partials, [pb][chunk][d] (8MB)
__device__ float g_cos[PP * BB];              // cosine sims
__device__ float g_htab[PP * VV * HH];        // tanh(tables@w1+b1) [512][42]

__device__ __forceinline__ ull fma2(ull a, ull b, ull c) {
    ull d;
    asm("fma.rn.f32x2 %0, %1, %2, %3;" : "=l"(d) : "l"(a), "l"(b), "l"(c));
    return d;
}
__device__ __forceinline__ ull pack2(float lo, float hi) {
    float2 f = make_float2(lo, hi);
    ull u; memcpy(&u, &f, 8); return u;
}
__device__ __forceinline__ float2 unpack2(ull u) {
    float2 f; memcpy(&f, &u, 8); return f;
}

// ---------------- kernel 1: knorm — n[p,b,s]; tail: w1 transpose ----------------
__global__ __launch_bounds__(256) void knorm(const float* __restrict__ ctx,
                                             const float* __restrict__ lora,
                                             const float* __restrict__ w1) {
    __shared__ float su[PP * DD];
    int t = threadIdx.x, warp = t >> 5, lane = t & 31;
    for (int i = t; i < PP * DD; i += 256) {
        float e = lora[i];
        su[i] = e / fmaxf(2.0f * fabsf(e), EPSF);
    }
    __syncthreads();
    int row = blockIdx.x * 8 + warp;          // 1024 blocks x 8 warps = 8192 rows
    int b = row >> 11, s = row & 2047;
    const float4* x4 = reinterpret_cast<const float4*>(ctx + (size_t)row * DD);
    float nrm2 = 0.f;
    float dot[PP];
#pragma unroll
    for (int p = 0; p < PP; p++) dot[p] = 0.f;
#pragma unroll
    for (int it = 0; it < 8; it++) {
        int q = lane + it * 32;
        float4 x = x4[q];
        nrm2 += x.x * x.x + x.y * x.y + x.z * x.z + x.w * x.w;
#pragma unroll
        for (int p = 0; p < PP; p++) {
            float4 u = reinterpret_cast<const float4*>(su + p * DD)[q];
            dot[p] += x.x * u.x + x.y * u.y + x.z * u.z + x.w * u.w;
        }
    }
#pragma unroll
    for (int o = 16; o; o >>= 1) {
        nrm2 += __shfl_xor_sync(0xffffffffu, nrm2, o);
#pragma unroll
        for (int p = 0; p < PP; p++) dot[p] += __shfl_xor_sync(0xffffffffu, dot[p], o);
    }
    if (lane < PP) {
        float dl = 0.f;
#pragma unroll
        for (int p = 0; p < PP; p++) if (lane == p) dl = dot[p];
        float v = dl / fmaxf(sqrtf(nrm2), EPSF);
        float c = fmaxf(v, 0.f);
        g_n[((size_t)lane * BB + b) * SS + s] = c / fmaxf(SQRT_S * c, EPSF);
    }
    // tail: transpose w1 -> g_w1t  (168*256 = 43008 = D*H exactly)
    if (blockIdx.x < 168) {
        int idx = blockIdx.x * 256 + t;
        int d = idx / HH, h = idx - d * HH;
        g_w1t[(size_t)h * DD + d] = w1[idx];
    }
}

// ---------------- kernel 2: softmax over s (per p,b) -> weights ----------------
__global__ __launch_bounds__(256) void ksoft() {
    __shared__ float sn[SS];
    __shared__ float red[256];
    int pb = blockIdx.x;
    int t = threadIdx.x;
    const float* np = g_n + (size_t)pb * SS;
    float m = -1e30f;
    for (int i = t; i < SS; i += 256) { float v = np[i]; sn[i] = v; m = fmaxf(m, v); }
    red[t] = m; __syncthreads();
    for (int o = 128; o; o >>= 1) { if (t < o) red[t] = fmaxf(red[t], red[t + o]); __syncthreads(); }
    m = red[0]; __syncthreads();
    float sum = 0.f;
    for (int i = t; i < SS; i += 256) sum += expf(sn[i] - m);
    red[t] = sum; __syncthreads();
    for (int o = 128; o; o >>= 1) { if (t < o) red[t] += red[t + o]; __syncthreads(); }
    float inv = 1.0f / red[0];
    for (int i = t; i < SS; i += 256) g_wsm[(size_t)pb * SS + i] = expf(sn[i] - m) * inv;
}

// ---------------- kernel 3: kavph — kavp (blk<512) || htab (512<=blk<640) ----------------
__global__ __launch_bounds__(256) void kavph(const float* __restrict__ ctx,
                                             const float* __restrict__ tables,
                                             const float* __restrict__ b1) {
    __shared__ float smem[4 * DD];    // union: kavp uses first 256 floats; htab uses all 16KB
    int blk = blockIdx.x;
    int t = threadIdx.x, warp = t >> 5, lane = t & 31;
    if (blk < 512) {
        // ---- kavp tile: 32 s-rows, half of D ----
        float* ws = smem;
        int schunk = blk & 63, rem = blk >> 6;
        int b = rem & 3, dh = rem >> 2;
        ws[t] = g_wsm[((size_t)(t & 7) * BB + b) * SS + schunk * 32 + (t >> 3)];
        __syncthreads();
        float2 acc[PP];
#pragma unroll
        for (int p = 0; p < PP; p++) acc[p] = make_float2(0.f, 0.f);
        const float2* cp = reinterpret_cast<const float2*>(ctx) +
                           ((size_t)b * SS + schunk * 32) * 512 + dh * 256 + t;
#pragma unroll
        for (int sl = 0; sl < 32; sl += 8) {
            float2 x[8];
#pragma unroll
            for (int r = 0; r < 8; r++) x[r] = cp[(size_t)(sl + r) * 512];
#pragma unroll
            for (int p = 0; p < PP; p++) {
#pragma unroll
                for (int r = 0; r < 8; r++) {
                    float w = ws[(sl + r) * 8 + p];
                    acc[p].x += w * x[r].x;
                    acc[p].y += w * x[r].y;
                }
            }
        }
#pragma unroll
        for (int p = 0; p < PP; p++)
            reinterpret_cast<float2*>(g_avp)[((size_t)(p * BB + b) * NSC + schunk) * 512 + dh * 256 + t] = acc[p];
    } else {
        // ---- htab: 4 token rows per block ----
        float* tok = smem;
        int quad = blk - 512;                  // 0..127 -> rows quad*4 .. +3
        const float* src = tables + (size_t)quad * 4 * DD;
        for (int i = t; i < 4 * DD; i += 256) tok[i] = src[i];
        __syncthreads();
#pragma unroll
        for (int j = 0; j < 6; j++) {
            int h = warp + j * 8;
            if (h < HH) {
                const float4* wr = reinterpret_cast<const float4*>(g_w1t + (size_t)h * DD);
                float d0 = 0.f, d1 = 0.f, d2 = 0.f, d3 = 0.f;
#pragma unroll
                for (int it = 0; it < 8; it++) {
                    int q = lane + it * 32;
                    float4 wv = wr[q];
                    float4 t0 = reinterpret_cast<const float4*>(tok)[q];
                    float4 t1 = reinterpret_cast<const float4*>(tok + DD)[q];
                    float4 t2 = reinterpret_cast<const float4*>(tok + 2 * DD)[q];
                    float4 t3 = reinterpret_cast<const float4*>(tok + 3 * DD)[q];
                    d0 += wv.x * t0.x + wv.y * t0.y + wv.z * t0.z + wv.w * t0.w;
                    d1 += wv.x * t1.x + wv.y * t1.y + wv.z * t1.z + wv.w * t1.w;
                    d2 += wv.x * t2.x + wv.y * t2.y + wv.z * t2.z + wv.w * t2.w;
                    d3 += wv.x * t3.x + wv.y * t3.y + wv.z * t3.z + wv.w * t3.w;
                }
#pragma unroll
                for (int o = 16; o; o >>= 1) {
                    d0 += __shfl_xor_sync(0xffffffffu, d0, o);
                    d1 += __shfl_xor_sync(0xffffffffu, d1, o);
                    d2 += __shfl_xor_sync(0xffffffffu, d2, o);
                    d3 += __shfl_xor_sync(0xffffffffu, d3, o);
                }
                if (lane == 0) {
                    float bh = b1[h];
                    g_htab[(size_t)(quad * 4 + 0) * HH + h] = tanhf(d0 + bh);
                    g_htab[(size_t)(quad * 4 + 1) * HH + h] = tanhf(d1 + bh);
                    g_htab[(size_t)(quad * 4 + 2) * HH + h] = tanhf(d2 + bh);
                    g_htab[(size_t)(quad * 4 + 3) * HH + h] = tanhf(d3 + bh);
                }
            }
        }
    }
}

// ---------------- kernel 4: kcos — reduce avp + cosine per (p,b) ----------------
__global__ __launch_bounds__(256) void kcos(const float* __restrict__ lora) {
    __shared__ float red3[24];
    int pb = blockIdx.x, p = pb >> 2;
    int t = threadIdx.x, warp = t >> 5, lane = t & 31;
    const float4* av4 = reinterpret_cast<const float4*>(g_avp) + (size_t)pb * NSC * 256 + t;
    float4 s = make_float4(0.f, 0.f, 0.f, 0.f);
#pragma unroll
    for (int c0 = 0; c0 < NSC; c0 += 16) {
        float4 x[16];
#pragma unroll
        for (int c = 0; c < 16; c++) x[c] = av4[(size_t)(c0 + c) * 256];
#pragma unroll
        for (int c = 0; c < 16; c++) {
            s.x += x[c].x; s.y += x[c].y; s.z += x[c].z; s.w += x[c].w;
        }
    }
    float4 e = reinterpret_cast<const float4*>(lora + (size_t)p * DD)[t];
    float dot = e.x * s.x + e.y * s.y + e.z * s.z + e.w * s.w;
    float an2 = s.x * s.x + s.y * s.y + s.z * s.z + s.w * s.w;
    float en2 = e.x * e.x + e.y * e.y + e.z * e.z + e.w * e.w;
#pragma unroll
    for (int o = 16; o; o >>= 1) {
        dot += __shfl_xor_sync(0xffffffffu, dot, o);
        an2 += __shfl_xor_sync(0xffffffffu, an2, o);
        en2 += __shfl_xor_sync(0xffffffffu, en2, o);
    }
    if (lane == 0) { red3[warp] = dot; red3[8 + warp] = an2; red3[16 + warp] = en2; }
    __syncthreads();
    if (t == 0) {
        float D = 0.f, A = 0.f, E = 0.f;
#pragma unroll
        for (int w = 0; w < 8; w++) { D += red3[w]; A += red3[8 + w]; E += red3[16 + w]; }
        g_cos[pb] = D / fmaxf(sqrtf(E) * sqrtf(A), COSEPS);
    }
}

// ---------------- kernel 5: kout — gates + hbar inline, then hbar @ w2 + b2 ----------
// 64 rows per block (blockIdx.y of 4), 256 k per block (blockIdx.x of 192). 128 threads.
__global__ __launch_bounds__(128, 4) void kout(const int* __restrict__ prefix,
                                               const float* __restrict__ w2,
                                               const float* __restrict__ b2,
                                               float* __restrict__ out) {
    __shared__ float sgate[32];
    __shared__ __align__(16) ull hb2[64 * HH];   // hbar duplicated {v,v}, [row][h]
    int r0 = blockIdx.y * 64;
    int t = threadIdx.x;
    if (t < 32) {
        int bq = t >> 3, p = t & 7;
        float x[PP], m = -1e30f;
#pragma unroll
        for (int pp = 0; pp < PP; pp++) { x[pp] = g_cos[pp * BB + bq]; m = fmaxf(m, x[pp]); }
        float z = 0.f;
#pragma unroll
        for (int pp = 0; pp < PP; pp++) { x[pp] = expf(x[pp] - m); z += x[pp]; }
#pragma unroll
        for (int pp = 0; pp < PP; pp++) x[pp] /= z;        // s_t
        m = -1e30f;
#pragma unroll
        for (int pp = 0; pp < PP; pp++) m = fmaxf(m, x[pp]);
        z = 0.f;
#pragma unroll
        for (int pp = 0; pp < PP; pp++) { x[pp] = expf(x[pp] - m); z += x[pp]; }
        sgate[t] = x[p] / z;                                // gate[bq][p]
    }
    __syncthreads();
    for (int i = t; i < 64 * HH; i += 128) {
        int r = i / HH, h = i - r * HH;
        int bv = r0 + r;
        int pf = prefix[bv];
        int bq = bv >> 6;
        float s = 0.f;
#pragma unroll
        for (int p = 0; p < PP; p++)
            s += sgate[bq * 8 + p] * g_htab[((size_t)p * VV + pf) * HH + h];
        hb2[i] = pack2(s, s);
    }
    __syncthreads();
    int kp = blockIdx.x * 256 + t * 2;
    ull wcol[HH];
#pragma unroll
    for (int h = 0; h < HH; h++) {
        float2 wv = *reinterpret_cast<const float2*>(w2 + (size_t)h * KK + kp);
        wcol[h] = pack2(wv.x, wv.y);
    }
    float2 bv2 = *reinterpret_cast<const float2*>(b2 + kp);
    ull binit = pack2(bv2.x, bv2.y);
    for (int rg = 0; rg < 64; rg += 4) {
        ull a0 = binit, a1 = binit, a2 = binit, a3 = binit;
#pragma unroll
        for (int hp = 0; hp < HH / 2; hp++) {
            // LDS.128: two h-pairs per row per load
            ulonglong2 h0 = *reinterpret_cast<const ulonglong2*>(&hb2[(rg + 0) * HH + 2 * hp]);
            ulonglong2 h1 = *reinterpret_cast<const ulonglong2*>(&hb2[(rg + 1) * HH + 2 * hp]);
            ulonglong2 h2 = *reinterpret_cast<const ulonglong2*>(&hb2[(rg + 2) * HH + 2 * hp]);
            ulonglong2 h3 = *reinterpret_cast<const ulonglong2*>(&hb2[(rg + 3) * HH + 2 * hp]);
            ull w0 = wcol[2 * hp], w1v = wcol[2 * hp + 1];
            a0 = fma2(w0, h0.x, a0); a0 = fma2(w1v, h0.y, a0);
            a1 = fma2(w0, h1.x, a1); a1 = fma2(w1v, h1.y, a1);
            a2 = fma2(w0, h2.x, a2); a2 = fma2(w1v, h2.y, a2);
            a3 = fma2(w0, h3.x, a3); a3 = fma2(w1v, h3.y, a3);
        }
        *reinterpret_cast<float2*>(out + (size_t)(r0 + rg + 0) * KK + kp) = unpack2(a0);
        *reinterpret_cast<float2*>(out + (size_t)(r0 + rg + 1) * KK + kp) = unpack2(a1);
        *reinterpret_cast<float2*>(out + (size_t)(r0 + rg + 2) * KK + kp) = unpack2(a2);
        *reinterpret_cast<float2*>(out + (size_t)(r0 + rg + 3) * KK + kp) = unpack2(a3);
    }
}

// ---------------- launcher ----------------
extern "C" void kernel_launch(void* const* d_in, const int* in_sizes, int n_in,
                              void* d_out, int out_size) {
    const int* prefix = nullptr;
    const float *ctx = nullptr, *tables = nullptr, *lora = nullptr;
    const float *w1 = nullptr, *b1 = nullptr, *w2 = nullptr, *b2 = nullptr;
    for (int i = 0; i < n_in; i++) {
        switch (in_sizes[i]) {
            case 256:     prefix = (const int*)d_in[i];   break;  // (B,V) int32
            case 8388608: ctx    = (const float*)d_in[i]; break;  // (B,S,D)
            case 524288:  tables = (const float*)d_in[i]; break;  // (P,V,D)
            case 8192:    lora   = (const float*)d_in[i]; break;  // (P,D)
            case 43008:   w1     = (const float*)d_in[i]; break;  // (D,H)
            case 42:      b1     = (const float*)d_in[i]; break;  // (H,)
            case 2064384: w2     = (const float*)d_in[i]; break;  // (H,K)
            case 49152:   b2     = (const float*)d_in[i]; break;  // (K,)
        }
    }
    float* out = (float*)d_out;

    knorm<<<1024, 256>>>(ctx, lora, w1);
    ksoft<<<32, 256>>>();
    kavph<<<640, 256>>>(ctx, tables, b1);
    kcos<<<32, 256>>>(lora);
    kout<<<dim3(192, 4), 128>>>(prefix, w2, b2, out);
}

// round 9
// speedup vs baseline: 1.3909x; 1.3909x over previous
#include <cuda_runtime.h>
#include <math.h>
#include <string.h>

#define BB 4
#define SS 2048
#define VV 64
#define DD 1024
#define PP 8
#define HH 42
#define KK 49152
#define EPSF 1e-12f
#define COSEPS 1e-8f
#define SQRT_S 45.254834f   // sqrt(2048)

typedef unsigned long long ull;

// ---------------- scratch (static device globals; no allocs allowed) ----------------
__device__ float g_w1t[HH * DD];              // w1 transposed [H][D]
__device__ float g_n[PP * BB * SS];           // n values
__device__ float g_wsm[PP * BB * SS];         // softmax weights over s
__device__ float4 g_cred[PP * BB * 32];       // cos partials {dot, an2, en2, 0} per (pb, dchunk)
__device__ float g_htab[PP * VV * HH];        // tanh(tables@w1+b1) [512][42]

__device__ __forceinline__ ull fma2(ull a, ull b, ull c) {
    ull d;
    asm("fma.rn.f32x2 %0, %1, %2, %3;" : "=l"(d) : "l"(a), "l"(b), "l"(c));
    return d;
}
__device__ __forceinline__ ull pack2(float lo, float hi) {
    float2 f = make_float2(lo, hi);
    ull u; memcpy(&u, &f, 8); return u;
}
__device__ __forceinline__ float2 unpack2(ull u) {
    float2 f; memcpy(&f, &u, 8); return f;
}

// ---------------- kernel 1: knorm — n[p,b,s]; tail: w1 transpose ----------------
__global__ __launch_bounds__(256) void knorm(const float* __restrict__ ctx,
                                             const float* __restrict__ lora,
                                             const float* __restrict__ w1) {
    __shared__ float su[PP * DD];
    int t = threadIdx.x, warp = t >> 5, lane = t & 31;
    for (int i = t; i < PP * DD; i += 256) {
        float e = lora[i];
        su[i] = e / fmaxf(2.0f * fabsf(e), EPSF);
    }
    __syncthreads();
    int row = blockIdx.x * 8 + warp;          // 1024 blocks x 8 warps = 8192 rows
    int b = row >> 11, s = row & 2047;
    const float4* x4 = reinterpret_cast<const float4*>(ctx + (size_t)row * DD);
    float nrm2 = 0.f;
    float dot[PP];
#pragma unroll
    for (int p = 0; p < PP; p++) dot[p] = 0.f;
#pragma unroll
    for (int it = 0; it < 8; it++) {
        int q = lane + it * 32;
        float4 x = x4[q];
        nrm2 += x.x * x.x + x.y * x.y + x.z * x.z + x.w * x.w;
#pragma unroll
        for (int p = 0; p < PP; p++) {
            float4 u = reinterpret_cast<const float4*>(su + p * DD)[q];
            dot[p] += x.x * u.x + x.y * u.y + x.z * u.z + x.w * u.w;
        }
    }
#pragma unroll
    for (int o = 16; o; o >>= 1) {
        nrm2 += __shfl_xor_sync(0xffffffffu, nrm2, o);
#pragma unroll
        for (int p = 0; p < PP; p++) dot[p] += __shfl_xor_sync(0xffffffffu, dot[p], o);
    }
    if (lane < PP) {
        float dl = 0.f;
#pragma unroll
        for (int p = 0; p < PP; p++) if (lane == p) dl = dot[p];
        float v = dl / fmaxf(sqrtf(nrm2), EPSF);
        float c = fmaxf(v, 0.f);
        g_n[((size_t)lane * BB + b) * SS + s] = c / fmaxf(SQRT_S * c, EPSF);
    }
    // tail: transpose w1 -> g_w1t  (168*256 = 43008 = D*H exactly)
    if (blockIdx.x < 168) {
        int idx = blockIdx.x * 256 + t;
        int d = idx / HH, h = idx - d * HH;
        g_w1t[(size_t)h * DD + d] = w1[idx];
    }
}

// ---------------- kernel 2: ksofth — softmax (blk<32) || htab 4 rows (32<=blk<160) ----
__global__ __launch_bounds__(256) void ksofth(const float* __restrict__ tables,
                                              const float* __restrict__ b1) {
    __shared__ float smem[4 * DD];            // 16KB union
    int blk = blockIdx.x;
    int t = threadIdx.x, warp = t >> 5, lane = t & 31;
    if (blk < 32) {
        float* sn = smem;                     // [SS]
        float* red = smem + SS;               // [256]
        int pb = blk;
        const float* np = g_n + (size_t)pb * SS;
        float m = -1e30f;
        for (int i = t; i < SS; i += 256) { float v = np[i]; sn[i] = v; m = fmaxf(m, v); }
        red[t] = m; __syncthreads();
        for (int o = 128; o; o >>= 1) { if (t < o) red[t] = fmaxf(red[t], red[t + o]); __syncthreads(); }
        m = red[0]; __syncthreads();
        float sum = 0.f;
        for (int i = t; i < SS; i += 256) sum += expf(sn[i] - m);
        red[t] = sum; __syncthreads();
        for (int o = 128; o; o >>= 1) { if (t < o) red[t] += red[t + o]; __syncthreads(); }
        float inv = 1.0f / red[0];
        for (int i = t; i < SS; i += 256) g_wsm[(size_t)pb * SS + i] = expf(sn[i] - m) * inv;
    } else {
        float* tok = smem;
        int quad = blk - 32;                  // 0..127 -> token rows quad*4 .. +3
        const float* src = tables + (size_t)quad * 4 * DD;
        for (int i = t; i < 4 * DD; i += 256) tok[i] = src[i];
        __syncthreads();
#pragma unroll
        for (int j = 0; j < 6; j++) {
            int h = warp + j * 8;
            if (h < HH) {
                const float4* wr = reinterpret_cast<const float4*>(g_w1t + (size_t)h * DD);
                float d0 = 0.f, d1 = 0.f, d2 = 0.f, d3 = 0.f;
#pragma unroll
                for (int it = 0; it < 8; it++) {
                    int q = lane + it * 32;
                    float4 wv = wr[q];
                    float4 t0 = reinterpret_cast<const float4*>(tok)[q];
                    float4 t1 = reinterpret_cast<const float4*>(tok + DD)[q];
                    float4 t2 = reinterpret_cast<const float4*>(tok + 2 * DD)[q];
                    float4 t3 = reinterpret_cast<const float4*>(tok + 3 * DD)[q];
                    d0 += wv.x * t0.x + wv.y * t0.y + wv.z * t0.z + wv.w * t0.w;
                    d1 += wv.x * t1.x + wv.y * t1.y + wv.z * t1.z + wv.w * t1.w;
                    d2 += wv.x * t2.x + wv.y * t2.y + wv.z * t2.z + wv.w * t2.w;
                    d3 += wv.x * t3.x + wv.y * t3.y + wv.z * t3.z + wv.w * t3.w;
                }
#pragma unroll
                for (int o = 16; o; o >>= 1) {
                    d0 += __shfl_xor_sync(0xffffffffu, d0, o);
                    d1 += __shfl_xor_sync(0xffffffffu, d1, o);
                    d2 += __shfl_xor_sync(0xffffffffu, d2, o);
                    d3 += __shfl_xor_sync(0xffffffffu, d3, o);
                }
                if (lane == 0) {
                    float bh = b1[h];
                    g_htab[(size_t)(quad * 4 + 0) * HH + h] = tanhf(d0 + bh);
                    g_htab[(size_t)(quad * 4 + 1) * HH + h] = tanhf(d1 + bh);
                    g_htab[(size_t)(quad * 4 + 2) * HH + h] = tanhf(d2 + bh);
                    g_htab[(size_t)(quad * 4 + 3) * HH + h] = tanhf(d3 + bh);
                }
            }
        }
    }
}

// ---------------- kernel 3: kavd — direct a_v + cos partials ----------------
// grid 128: b = blk&3, dchunk = blk>>2 (32 d's). 512 threads: 16 warps x 128-row s-slices.
// dyn smem: ws[8*2048] (64KB) + red[16*8*32] (16KB) = 80KB
__global__ __launch_bounds__(512) void kavd(const float* __restrict__ ctx,
                                            const float* __restrict__ lora) {
    extern __shared__ float dsm[];
    float* ws = dsm;                  // [p][s]
    float* red = dsm + PP * SS;       // [warp][p][lane]
    int b = blockIdx.x & 3, dchunk = blockIdx.x >> 2;
    int t = threadIdx.x, w = t >> 5, lane = t & 31;
    for (int i = t; i < PP * SS; i += 512) {
        int p = i >> 11, s = i & 2047;
        ws[i] = g_wsm[((size_t)p * BB + b) * SS + s];
    }
    __syncthreads();
    int d = dchunk * 32 + lane;
    const float* cb = ctx + (size_t)b * SS * DD + d;
    int s0 = w * 128;
    float acc[PP];
#pragma unroll
    for (int p = 0; p < PP; p++) acc[p] = 0.f;
    for (int sb = 0; sb < 128; sb += 16) {
        float x[16];
#pragma unroll
        for (int r = 0; r < 16; r++) x[r] = cb[(size_t)(s0 + sb + r) * DD];
#pragma unroll
        for (int r = 0; r < 16; r++) {
            int s = s0 + sb + r;
            float xs = x[r];
#pragma unroll
            for (int p = 0; p < PP; p++) acc[p] += ws[p * SS + s] * xs;
        }
    }
#pragma unroll
    for (int p = 0; p < PP; p++) red[(w * PP + p) * 32 + lane] = acc[p];
    __syncthreads();
    if (w < PP) {
        int p = w;
        float av = 0.f;
#pragma unroll
        for (int ww = 0; ww < 16; ww++) av += red[(ww * PP + p) * 32 + lane];
        float e = lora[(size_t)p * DD + d];
        float dotv = e * av, an2 = av * av, en2 = e * e;
#pragma unroll
        for (int o = 16; o; o >>= 1) {
            dotv += __shfl_xor_sync(0xffffffffu, dotv, o);
            an2  += __shfl_xor_sync(0xffffffffu, an2, o);
            en2  += __shfl_xor_sync(0xffffffffu, en2, o);
        }
        if (lane == 0)
            g_cred[(p * BB + b) * 32 + dchunk] = make_float4(dotv, an2, en2, 0.f);
    }
}

// ---------------- kernel 4: kout — cos+gates + hbar inline, then hbar @ w2 + b2 ------
// 64 rows per block (blockIdx.y of 4), 256 k per block (blockIdx.x of 192). 128 threads.
__global__ __launch_bounds__(128, 4) void kout(const int* __restrict__ prefix,
                                               const float* __restrict__ w2,
                                               const float* __restrict__ b2,
                                               float* __restrict__ out) {
    __shared__ float scos[32];
    __shared__ float sgate[32];
    __shared__ ull hb2[64 * HH];   // hbar duplicated {v,v}, [row][h]
    int r0 = blockIdx.y * 64;
    int t = threadIdx.x;
    if (t < 32) {
        // cos from cred partials
        float D = 0.f, A = 0.f, E = 0.f;
#pragma unroll 8
        for (int c = 0; c < 32; c++) {
            float4 f = g_cred[t * 32 + c];
            D += f.x; A += f.y; E += f.z;
        }
        scos[t] = D / fmaxf(sqrtf(E) * sqrtf(A), COSEPS);   // scos[p*BB+b]
        __syncwarp();
        // double softmax over p for batch bq = t>>3; store gate for p = t&7
        int bq = t >> 3, p = t & 7;
        float x[PP], m = -1e30f;
#pragma unroll
        for (int pp = 0; pp < PP; pp++) { x[pp] = scos[pp * BB + bq]; m = fmaxf(m, x[pp]); }
        float z = 0.f;
#pragma unroll
        for (int pp = 0; pp < PP; pp++) { x[pp] = expf(x[pp] - m); z += x[pp]; }
#pragma unroll
        for (int pp = 0; pp < PP; pp++) x[pp] /= z;        // s_t
        m = -1e30f;
#pragma unroll
        for (int pp = 0; pp < PP; pp++) m = fmaxf(m, x[pp]);
        z = 0.f;
#pragma unroll
        for (int pp = 0; pp < PP; pp++) { x[pp] = expf(x[pp] - m); z += x[pp]; }
        sgate[t] = x[p] / z;                                // gate[bq][p]
    }
    __syncthreads();
    for (int i = t; i < 64 * HH; i += 128) {
        int r = i / HH, h = i - r * HH;
        int bv = r0 + r;
        int pf = prefix[bv];
        int bq = bv >> 6;
        float s = 0.f;
#pragma unroll
        for (int p = 0; p < PP; p++)
            s += sgate[bq * 8 + p] * g_htab[((size_t)p * VV + pf) * HH + h];
        hb2[i] = pack2(s, s);
    }
    __syncthreads();
    int kp = blockIdx.x * 256 + t * 2;
    ull wcol[HH];
#pragma unroll
    for (int h = 0; h < HH; h++) {
        float2 wv = *reinterpret_cast<const float2*>(w2 + (size_t)h * KK + kp);
        wcol[h] = pack2(wv.x, wv.y);
    }
    float2 bv2 = *reinterpret_cast<const float2*>(b2 + kp);
    ull binit = pack2(bv2.x, bv2.y);
    for (int rg = 0; rg < 64; rg += 4) {
        ull a0 = binit, a1 = binit, a2 = binit, a3 = binit;
#pragma unroll
        for (int h = 0; h < HH; h++) {
            a0 = fma2(wcol[h], hb2[(rg + 0) * HH + h], a0);
            a1 = fma2(wcol[h], hb2[(rg + 1) * HH + h], a1);
            a2 = fma2(wcol[h], hb2[(rg + 2) * HH + h], a2);
            a3 = fma2(wcol[h], hb2[(rg + 3) * HH + h], a3);
        }
        *reinterpret_cast<float2*>(out + (size_t)(r0 + rg + 0) * KK + kp) = unpack2(a0);
        *reinterpret_cast<float2*>(out + (size_t)(r0 + rg + 1) * KK + kp) = unpack2(a1);
        *reinterpret_cast<float2*>(out + (size_t)(r0 + rg + 2) * KK + kp) = unpack2(a2);
        *reinterpret_cast<float2*>(out + (size_t)(r0 + rg + 3) * KK + kp) = unpack2(a3);
    }
}

// ---------------- launcher ----------------
extern "C" void kernel_launch(void* const* d_in, const int* in_sizes, int n_in,
                              void* d_out, int out_size) {
    const int* prefix = nullptr;
    const float *ctx = nullptr, *tables = nullptr, *lora = nullptr;
    const float *w1 = nullptr, *b1 = nullptr, *w2 = nullptr, *b2 = nullptr;
    for (int i = 0; i < n_in; i++) {
        switch (in_sizes[i]) {
            case 256:     prefix = (const int*)d_in[i];   break;  // (B,V) int32
            case 8388608: ctx    = (const float*)d_in[i]; break;  // (B,S,D)
            case 524288:  tables = (const float*)d_in[i]; break;  // (P,V,D)
            case 8192:    lora   = (const float*)d_in[i]; break;  // (P,D)
            case 43008:   w1     = (const float*)d_in[i]; break;  // (D,H)
            case 42:      b1     = (const float*)d_in[i]; break;  // (H,)
            case 2064384: w2     = (const float*)d_in[i]; break;  // (H,K)
            case 49152:   b2     = (const float*)d_in[i]; break;  // (K,)
        }
    }
    float* out = (float*)d_out;

    const int kavd_smem = (PP * SS + 16 * PP * 32) * 4;   // 81920 B
    cudaFuncSetAttribute(kavd, cudaFuncAttributeMaxDynamicSharedMemorySize, kavd_smem);

    knorm<<<1024, 256>>>(ctx, lora, w1);
    ksofth<<<160, 256>>>(tables, b1);
    kavd<<<128, 512, kavd_smem>>>(ctx, lora);
    kout<<<dim3(192, 4), 128>>>(prefix, w2, b2, out);   // 4th launch -> profiled
}

// round 10
// speedup vs baseline: 1.3932x; 1.0017x over previous
#include <cuda_runtime.h>
#include <math.h>
#include <string.h>

#define BB 4
#define SS 2048
#define VV 64
#define DD 1024
#define PP 8
#define HH 42
#define KK 49152
#define EPSF 1e-12f
#define COSEPS 1e-8f
#define SQRT_S 45.254834f   // sqrt(2048)

typedef unsigned long long ull;

// ---------------- scratch (static device globals; no allocs allowed) ----------------
__device__ float g_w1t[HH * DD];              // w1 transposed [H][D]
__device__ float g_n[PP * BB * SS];           // n values
__device__ float g_wsm[PP * BB * SS];         // softmax weights over s
__device__ float4 g_cred[PP * BB * 32];       // cos partials {dot, an2, en2, 0} per (pb, dchunk)
__device__ float g_htab[PP * VV * HH];        // tanh(tables@w1+b1) [512][42]

__device__ __forceinline__ ull fma2(ull a, ull b, ull c) {
    ull d;
    asm("fma.rn.f32x2 %0, %1, %2, %3;" : "=l"(d) : "l"(a), "l"(b), "l"(c));
    return d;
}
__device__ __forceinline__ ull pack2(float lo, float hi) {
    float2 f = make_float2(lo, hi);
    ull u; memcpy(&u, &f, 8); return u;
}
__device__ __forceinline__ float2 unpack2(ull u) {
    float2 f; memcpy(&f, &u, 8); return f;
}

// ---------------- kernel 1: knorm — n[p,b,s]; tail: w1 transpose ----------------
__global__ __launch_bounds__(256) void knorm(const float* __restrict__ ctx,
                                             const float* __restrict__ lora,
                                             const float* __restrict__ w1) {
    __shared__ float su[PP * DD];
    int t = threadIdx.x, warp = t >> 5, lane = t & 31;
    for (int i = t; i < PP * DD; i += 256) {
        float e = lora[i];
        su[i] = e / fmaxf(2.0f * fabsf(e), EPSF);
    }
    __syncthreads();
    int row = blockIdx.x * 8 + warp;          // 1024 blocks x 8 warps = 8192 rows
    int b = row >> 11, s = row & 2047;
    const float4* x4 = reinterpret_cast<const float4*>(ctx + (size_t)row * DD);
    float nrm2 = 0.f;
    float dot[PP];
#pragma unroll
    for (int p = 0; p < PP; p++) dot[p] = 0.f;
#pragma unroll
    for (int it = 0; it < 8; it++) {
        int q = lane + it * 32;
        float4 x = x4[q];
        nrm2 += x.x * x.x + x.y * x.y + x.z * x.z + x.w * x.w;
#pragma unroll
        for (int p = 0; p < PP; p++) {
            float4 u = reinterpret_cast<const float4*>(su + p * DD)[q];
            dot[p] += x.x * u.x + x.y * u.y + x.z * u.z + x.w * u.w;
        }
    }
#pragma unroll
    for (int o = 16; o; o >>= 1) {
        nrm2 += __shfl_xor_sync(0xffffffffu, nrm2, o);
#pragma unroll
        for (int p = 0; p < PP; p++) dot[p] += __shfl_xor_sync(0xffffffffu, dot[p], o);
    }
    if (lane < PP) {
        float dl = 0.f;
#pragma unroll
        for (int p = 0; p < PP; p++) if (lane == p) dl = dot[p];
        float v = dl / fmaxf(sqrtf(nrm2), EPSF);
        float c = fmaxf(v, 0.f);
        g_n[((size_t)lane * BB + b) * SS + s] = c / fmaxf(SQRT_S * c, EPSF);
    }
    // tail: transpose w1 -> g_w1t  (168*256 = 43008 = D*H exactly)
    if (blockIdx.x < 168) {
        int idx = blockIdx.x * 256 + t;
        int d = idx / HH, h = idx - d * HH;
        g_w1t[(size_t)h * DD + d] = w1[idx];
    }
}

// ---------------- kernel 2: ksofth — softmax (blk<32) || htab 8 rows (32<=blk<96) ----
__global__ __launch_bounds__(256) void ksofth(const float* __restrict__ tables,
                                              const float* __restrict__ b1) {
    __shared__ float smem[8 * DD];            // 32KB union
    int blk = blockIdx.x;
    int t = threadIdx.x, warp = t >> 5, lane = t & 31;
    if (blk < 32) {
        float* sn = smem;                     // [SS]
        float* red = smem + SS;               // [256]
        int pb = blk;
        const float* np = g_n + (size_t)pb * SS;
        float m = -1e30f;
        for (int i = t; i < SS; i += 256) { float v = np[i]; sn[i] = v; m = fmaxf(m, v); }
        red[t] = m; __syncthreads();
        for (int o = 128; o; o >>= 1) { if (t < o) red[t] = fmaxf(red[t], red[t + o]); __syncthreads(); }
        m = red[0]; __syncthreads();
        float sum = 0.f;
        for (int i = t; i < SS; i += 256) sum += expf(sn[i] - m);
        red[t] = sum; __syncthreads();
        for (int o = 128; o; o >>= 1) { if (t < o) red[t] += red[t + o]; __syncthreads(); }
        float inv = 1.0f / red[0];
        for (int i = t; i < SS; i += 256) g_wsm[(size_t)pb * SS + i] = expf(sn[i] - m) * inv;
    } else {
        float* tok = smem;
        int oct = blk - 32;                   // 0..63 -> token rows oct*8 .. +7
        const float* src = tables + (size_t)oct * 8 * DD;
        for (int i = t; i < 8 * DD; i += 256) tok[i] = src[i];
        __syncthreads();
#pragma unroll
        for (int j = 0; j < 6; j++) {
            int h = warp + j * 8;
            if (h < HH) {
                const float4* wr = reinterpret_cast<const float4*>(g_w1t + (size_t)h * DD);
                float dt[8];
#pragma unroll
                for (int r = 0; r < 8; r++) dt[r] = 0.f;
#pragma unroll
                for (int it = 0; it < 8; it++) {
                    int q = lane + it * 32;
                    float4 wv = wr[q];
#pragma unroll
                    for (int r = 0; r < 8; r++) {
                        float4 tv = reinterpret_cast<const float4*>(tok + r * DD)[q];
                        dt[r] += wv.x * tv.x + wv.y * tv.y + wv.z * tv.z + wv.w * tv.w;
                    }
                }
#pragma unroll
                for (int o = 16; o; o >>= 1)
#pragma unroll
                    for (int r = 0; r < 8; r++) dt[r] += __shfl_xor_sync(0xffffffffu, dt[r], o);
                if (lane < 8) {
                    float dl = 0.f;
#pragma unroll
                    for (int r = 0; r < 8; r++) if (lane == r) dl = dt[r];
                    g_htab[(size_t)(oct * 8 + lane) * HH + h] = tanhf(dl + b1[h]);
                }
            }
        }
    }
}

// ---------------- kernel 3: kavd — direct a_v + cos partials ----------------
// grid 128: b = blk&3, dchunk = blk>>2 (32 d's). 1024 threads: 32 warps x 64-row s-slices.
// dyn smem: ws[8*2048] (64KB) + red[32*8*32] (32KB) = 96KB
__global__ __launch_bounds__(1024) void kavd(const float* __restrict__ ctx,
                                             const float* __restrict__ lora) {
    extern __shared__ float dsm[];
    float* ws = dsm;                  // [p][s]
    float* red = dsm + PP * SS;       // [warp][p][lane]
    int b = blockIdx.x & 3, dchunk = blockIdx.x >> 2;
    int t = threadIdx.x, w = t >> 5, lane = t & 31;
    for (int i = t; i < PP * SS; i += 1024) {
        int p = i >> 11, s = i & 2047;
        ws[i] = g_wsm[((size_t)p * BB + b) * SS + s];
    }
    __syncthreads();
    int d = dchunk * 32 + lane;
    const float* cb = ctx + (size_t)b * SS * DD + d;
    int s0 = w * 64;
    float acc[PP];
#pragma unroll
    for (int p = 0; p < PP; p++) acc[p] = 0.f;
#pragma unroll
    for (int sb = 0; sb < 64; sb += 16) {
        float x[16];
#pragma unroll
        for (int r = 0; r < 16; r++) x[r] = cb[(size_t)(s0 + sb + r) * DD];
#pragma unroll
        for (int r = 0; r < 16; r++) {
            int s = s0 + sb + r;
            float xs = x[r];
#pragma unroll
            for (int p = 0; p < PP; p++) acc[p] += ws[p * SS + s] * xs;
        }
    }
#pragma unroll
    for (int p = 0; p < PP; p++) red[(w * PP + p) * 32 + lane] = acc[p];
    __syncthreads();
    if (w < PP) {
        int p = w;
        float av = 0.f;
#pragma unroll
        for (int ww = 0; ww < 32; ww++) av += red[(ww * PP + p) * 32 + lane];
        float e = lora[(size_t)p * DD + d];
        float dotv = e * av, an2 = av * av, en2 = e * e;
#pragma unroll
        for (int o = 16; o; o >>= 1) {
            dotv += __shfl_xor_sync(0xffffffffu, dotv, o);
            an2  += __shfl_xor_sync(0xffffffffu, an2, o);
            en2  += __shfl_xor_sync(0xffffffffu, en2, o);
        }
        if (lane == 0)
            g_cred[(p * BB + b) * 32 + dchunk] = make_float4(dotv, an2, en2, 0.f);
    }
}

// ---------------- kernel 4: kout — cos+gates + hbar inline, then hbar @ w2 + b2 ------
// 64 rows per block (blockIdx.y of 4), 256 k per block (blockIdx.x of 192). 128 threads.
__global__ __launch_bounds__(128, 4) void kout(const int* __restrict__ prefix,
                                               const float* __restrict__ w2,
                                               const float* __restrict__ b2,
                                               float* __restrict__ out) {
    __shared__ float scos[32];
    __shared__ float sgate[32];
    __shared__ __align__(16) ull hb2[64 * HH];   // hbar duplicated {v,v}, [row][h]
    int r0 = blockIdx.y * 64;
    int t = threadIdx.x;
    if (t < 32) {
        // cos from cred partials
        float D = 0.f, A = 0.f, E = 0.f;
#pragma unroll 8
        for (int c = 0; c < 32; c++) {
            float4 f = g_cred[t * 32 + c];
            D += f.x; A += f.y; E += f.z;
        }
        scos[t] = D / fmaxf(sqrtf(E) * sqrtf(A), COSEPS);   // scos[p*BB+b]
        __syncwarp();
        // double softmax over p for batch bq = t>>3; store gate for p = t&7
        int bq = t >> 3, p = t & 7;
        float x[PP], m = -1e30f;
#pragma unroll
        for (int pp = 0; pp < PP; pp++) { x[pp] = scos[pp * BB + bq]; m = fmaxf(m, x[pp]); }
        float z = 0.f;
#pragma unroll
        for (int pp = 0; pp < PP; pp++) { x[pp] = expf(x[pp] - m); z += x[pp]; }
#pragma unroll
        for (int pp = 0; pp < PP; pp++) x[pp] /= z;        // s_t
        m = -1e30f;
#pragma unroll
        for (int pp = 0; pp < PP; pp++) m = fmaxf(m, x[pp]);
        z = 0.f;
#pragma unroll
        for (int pp = 0; pp < PP; pp++) { x[pp] = expf(x[pp] - m); z += x[pp]; }
        sgate[t] = x[p] / z;                                // gate[bq][p]
    }
    __syncthreads();
    for (int i = t; i < 64 * HH; i += 128) {
        int r = i / HH, h = i - r * HH;
        int bv = r0 + r;
        int pf = prefix[bv];
        int bq = bv >> 6;
        float s = 0.f;
#pragma unroll
        for (int p = 0; p < PP; p++)
            s += sgate[bq * 8 + p] * g_htab[((size_t)p * VV + pf) * HH + h];
        hb2[i] = pack2(s, s);
    }
    __syncthreads();
    int kp = blockIdx.x * 256 + t * 2;
    ull wcol[HH];
#pragma unroll
    for (int h = 0; h < HH; h++) {
        float2 wv = *reinterpret_cast<const float2*>(w2 + (size_t)h * KK + kp);
        wcol[h] = pack2(wv.x, wv.y);
    }
    float2 bv2 = *reinterpret_cast<const float2*>(b2 + kp);
    ull binit = pack2(bv2.x, bv2.y);
    for (int rg = 0; rg < 64; rg += 4) {
        ull a0 = binit, a1 = binit, a2 = binit, a3 = binit;
#pragma unroll
        for (int hp = 0; hp < HH / 2; hp++) {
            // LDS.128: two h-values per smem load, each feeds 2 FFMA2
            ulonglong2 h0 = *reinterpret_cast<const ulonglong2*>(&hb2[(rg + 0) * HH + 2 * hp]);
            ulonglong2 h1 = *reinterpret_cast<const ulonglong2*>(&hb2[(rg + 1) * HH + 2 * hp]);
            ulonglong2 h2 = *reinterpret_cast<const ulonglong2*>(&hb2[(rg + 2) * HH + 2 * hp]);
            ulonglong2 h3 = *reinterpret_cast<const ulonglong2*>(&hb2[(rg + 3) * HH + 2 * hp]);
            ull w0 = wcol[2 * hp], w1v = wcol[2 * hp + 1];
            a0 = fma2(w0, h0.x, a0); a0 = fma2(w1v, h0.y, a0);
            a1 = fma2(w0, h1.x, a1); a1 = fma2(w1v, h1.y, a1);
            a2 = fma2(w0, h2.x, a2); a2 = fma2(w1v, h2.y, a2);
            a3 = fma2(w0, h3.x, a3); a3 = fma2(w1v, h3.y, a3);
        }
        *reinterpret_cast<float2*>(out + (size_t)(r0 + rg + 0) * KK + kp) = unpack2(a0);
        *reinterpret_cast<float2*>(out + (size_t)(r0 + rg + 1) * KK + kp) = unpack2(a1);
        *reinterpret_cast<float2*>(out + (size_t)(r0 + rg + 2) * KK + kp) = unpack2(a2);
        *reinterpret_cast<float2*>(out + (size_t)(r0 + rg + 3) * KK + kp) = unpack2(a3);
    }
}

// ---------------- launcher ----------------
extern "C" void kernel_launch(void* const* d_in, const int* in_sizes, int n_in,
                              void* d_out, int out_size) {
    const int* prefix = nullptr;
    const float *ctx = nullptr, *tables = nullptr, *lora = nullptr;
    const float *w1 = nullptr, *b1 = nullptr, *w2 = nullptr, *b2 = nullptr;
    for (int i = 0; i < n_in; i++) {
        switch (in_sizes[i]) {
            case 256:     prefix = (const int*)d_in[i];   break;  // (B,V) int32
            case 8388608: ctx    = (const float*)d_in[i]; break;  // (B,S,D)
            case 524288:  tables = (const float*)d_in[i]; break;  // (P,V,D)
            case 8192:    lora   = (const float*)d_in[i]; break;  // (P,D)
            case 43008:   w1     = (const float*)d_in[i]; break;  // (D,H)
            case 42:      b1     = (const float*)d_in[i]; break;  // (H,)
            case 2064384: w2     = (const float*)d_in[i]; break;  // (H,K)
            case 49152:   b2     = (const float*)d_in[i]; break;  // (K,)
        }
    }
    float* out = (float*)d_out;

    const int kavd_smem = (PP * SS + 32 * PP * 32) * 4;   // 98304 B
    cudaFuncSetAttribute(kavd, cudaFuncAttributeMaxDynamicSharedMemorySize, kavd_smem);

    knorm<<<1024, 256>>>(ctx, lora, w1);
    ksofth<<<96, 256>>>(tables, b1);
    kavd<<<128, 1024, kavd_smem>>>(ctx, lora);
    kout<<<dim3(192, 4), 128>>>(prefix, w2, b2, out);   // 4th launch -> profiled
}

// round 11
// speedup vs baseline: 1.3940x; 1.0006x over previous
#include <cuda_runtime.h>
#include <math.h>
#include <string.h>

#define BB 4
#define SS 2048
#define VV 64
#define DD 1024
#define PP 8
#define HH 42
#define KK 49152
#define EPSF 1e-12f
#define COSEPS 1e-8f
#define SQRT_S 45.254834f   // sqrt(2048)

typedef unsigned long long ull;

// ---------------- scratch (static device globals; no allocs allowed) ----------------
__device__ float g_w1t[HH * DD];              // w1 transposed [H][D]
__device__ float g_n[PP * BB * SS];           // n values
__device__ float g_wsm[PP * BB * SS];         // softmax weights over s
__device__ float4 g_cred[PP * BB * 32];       // cos partials {dot, an2, en2, 0} per (pb, dchunk)
__device__ float g_htab[PP * VV * HH];        // tanh(tables@w1+b1) [512][42]

__device__ __forceinline__ ull fma2(ull a, ull b, ull c) {
    ull d;
    asm("fma.rn.f32x2 %0, %1, %2, %3;" : "=l"(d) : "l"(a), "l"(b), "l"(c));
    return d;
}
__device__ __forceinline__ ull pack2(float lo, float hi) {
    float2 f = make_float2(lo, hi);
    ull u; memcpy(&u, &f, 8); return u;
}
__device__ __forceinline__ float2 unpack2(ull u) {
    float2 f; memcpy(&f, &u, 8); return f;
}

// ---------------- kernel 1: knorm — n[p,b,s]; tail: w1 transpose ----------------
__global__ __launch_bounds__(256) void knorm(const float* __restrict__ ctx,
                                             const float* __restrict__ lora,
                                             const float* __restrict__ w1) {
    __shared__ float su[PP * DD];
    int t = threadIdx.x, warp = t >> 5, lane = t & 31;
    for (int i = t; i < PP * DD; i += 256) {
        float e = lora[i];
        su[i] = e / fmaxf(2.0f * fabsf(e), EPSF);
    }
    __syncthreads();
    int row = blockIdx.x * 8 + warp;          // 1024 blocks x 8 warps = 8192 rows
    int b = row >> 11, s = row & 2047;
    const float4* x4 = reinterpret_cast<const float4*>(ctx + (size_t)row * DD);
    float nrm2 = 0.f;
    float dot[PP];
#pragma unroll
    for (int p = 0; p < PP; p++) dot[p] = 0.f;
#pragma unroll
    for (int it = 0; it < 8; it++) {
        int q = lane + it * 32;
        float4 x = x4[q];
        nrm2 += x.x * x.x + x.y * x.y + x.z * x.z + x.w * x.w;
#pragma unroll
        for (int p = 0; p < PP; p++) {
            float4 u = reinterpret_cast<const float4*>(su + p * DD)[q];
            dot[p] += x.x * u.x + x.y * u.y + x.z * u.z + x.w * u.w;
        }
    }
#pragma unroll
    for (int o = 16; o; o >>= 1) {
        nrm2 += __shfl_xor_sync(0xffffffffu, nrm2, o);
#pragma unroll
        for (int p = 0; p < PP; p++) dot[p] += __shfl_xor_sync(0xffffffffu, dot[p], o);
    }
    if (lane < PP) {
        float dl = 0.f;
#pragma unroll
        for (int p = 0; p < PP; p++) if (lane == p) dl = dot[p];
        float v = dl / fmaxf(sqrtf(nrm2), EPSF);
        float c = fmaxf(v, 0.f);
        g_n[((size_t)lane * BB + b) * SS + s] = c / fmaxf(SQRT_S * c, EPSF);
    }
    // tail: transpose w1 -> g_w1t  (168*256 = 43008 = D*H exactly)
    if (blockIdx.x < 168) {
        int idx = blockIdx.x * 256 + t;
        int d = idx / HH, h = idx - d * HH;
        g_w1t[(size_t)h * DD + d] = w1[idx];
    }
}

// ---------------- kernel 2: ksofth — softmax (blk<32) || htab 8 rows (32<=blk<96) ----
__global__ __launch_bounds__(256) void ksofth(const float* __restrict__ tables,
                                              const float* __restrict__ b1) {
    __shared__ float smem[8 * DD];            // 32KB union
    int blk = blockIdx.x;
    int t = threadIdx.x, warp = t >> 5, lane = t & 31;
    if (blk < 32) {
        float* sn = smem;                     // [SS]
        float* red = smem + SS;               // [256]
        int pb = blk;
        const float* np = g_n + (size_t)pb * SS;
        float m = -1e30f;
        for (int i = t; i < SS; i += 256) { float v = np[i]; sn[i] = v; m = fmaxf(m, v); }
        red[t] = m; __syncthreads();
        for (int o = 128; o; o >>= 1) { if (t < o) red[t] = fmaxf(red[t], red[t + o]); __syncthreads(); }
        m = red[0]; __syncthreads();
        float sum = 0.f;
        for (int i = t; i < SS; i += 256) sum += expf(sn[i] - m);
        red[t] = sum; __syncthreads();
        for (int o = 128; o; o >>= 1) { if (t < o) red[t] += red[t + o]; __syncthreads(); }
        float inv = 1.0f / red[0];
        for (int i = t; i < SS; i += 256) g_wsm[(size_t)pb * SS + i] = expf(sn[i] - m) * inv;
    } else {
        float* tok = smem;
        int oct = blk - 32;                   // 0..63 -> token rows oct*8 .. +7
        const float* src = tables + (size_t)oct * 8 * DD;
        for (int i = t; i < 8 * DD; i += 256) tok[i] = src[i];
        __syncthreads();
#pragma unroll
        for (int j = 0; j < 6; j++) {
            int h = warp + j * 8;
            if (h < HH) {
                const float4* wr = reinterpret_cast<const float4*>(g_w1t + (size_t)h * DD);
                float dt[8];
#pragma unroll
                for (int r = 0; r < 8; r++) dt[r] = 0.f;
#pragma unroll
                for (int it = 0; it < 8; it++) {
                    int q = lane + it * 32;
                    float4 wv = wr[q];
#pragma unroll
                    for (int r = 0; r < 8; r++) {
                        float4 tv = reinterpret_cast<const float4*>(tok + r * DD)[q];
                        dt[r] += wv.x * tv.x + wv.y * tv.y + wv.z * tv.z + wv.w * tv.w;
                    }
                }
#pragma unroll
                for (int o = 16; o; o >>= 1)
#pragma unroll
                    for (int r = 0; r < 8; r++) dt[r] += __shfl_xor_sync(0xffffffffu, dt[r], o);
                if (lane < 8) {
                    float dl = 0.f;
#pragma unroll
                    for (int r = 0; r < 8; r++) if (lane == r) dl = dt[r];
                    g_htab[(size_t)(oct * 8 + lane) * HH + h] = tanhf(dl + b1[h]);
                }
            }
        }
    }
}

// ---------------- kernel 3: kavd — direct a_v + cos partials ----------------
// grid 128: b = blk&3, dchunk = blk>>2 (32 d's). 1024 threads: 32 warps x 64-row s-slices.
// dyn smem: ws[8*2048] (64KB) + red[32*8*32] (32KB) = 96KB
__global__ __launch_bounds__(1024) void kavd(const float* __restrict__ ctx,
                                             const float* __restrict__ lora) {
    extern __shared__ float dsm[];
    float* ws = dsm;                  // [p][s]
    float* red = dsm + PP * SS;       // [warp][p][lane]
    int b = blockIdx.x & 3, dchunk = blockIdx.x >> 2;
    int t = threadIdx.x, w = t >> 5, lane = t & 31;
    for (int i = t; i < PP * SS; i += 1024) {
        int p = i >> 11, s = i & 2047;
        ws[i] = g_wsm[((size_t)p * BB + b) * SS + s];
    }
    __syncthreads();
    int d = dchunk * 32 + lane;
    const float* cb = ctx + (size_t)b * SS * DD + d;
    int s0 = w * 64;
    float acc[PP];
#pragma unroll
    for (int p = 0; p < PP; p++) acc[p] = 0.f;
#pragma unroll
    for (int sb = 0; sb < 64; sb += 16) {
        float x[16];
#pragma unroll
        for (int r = 0; r < 16; r++) x[r] = cb[(size_t)(s0 + sb + r) * DD];
#pragma unroll
        for (int r = 0; r < 16; r++) {
            int s = s0 + sb + r;
            float xs = x[r];
#pragma unroll
            for (int p = 0; p < PP; p++) acc[p] += ws[p * SS + s] * xs;
        }
    }
#pragma unroll
    for (int p = 0; p < PP; p++) red[(w * PP + p) * 32 + lane] = acc[p];
    __syncthreads();
    if (w < PP) {
        int p = w;
        float av = 0.f;
#pragma unroll
        for (int ww = 0; ww < 32; ww++) av += red[(ww * PP + p) * 32 + lane];
        float e = lora[(size_t)p * DD + d];
        float dotv = e * av, an2 = av * av, en2 = e * e;
#pragma unroll
        for (int o = 16; o; o >>= 1) {
            dotv += __shfl_xor_sync(0xffffffffu, dotv, o);
            an2  += __shfl_xor_sync(0xffffffffu, an2, o);
            en2  += __shfl_xor_sync(0xffffffffu, en2, o);
        }
        if (lane == 0)
            g_cred[(p * BB + b) * 32 + dchunk] = make_float4(dotv, an2, en2, 0.f);
    }
}

// ---------------- kernel 4: kout — cos+gates + hbar inline, then hbar @ w2 + b2 ------
// 64 rows per block (blockIdx.y of 4), 256 k per block (blockIdx.x of 192). 128 threads.
__global__ __launch_bounds__(128, 4) void kout(const int* __restrict__ prefix,
                                               const float* __restrict__ w2,
                                               const float* __restrict__ b2,
                                               float* __restrict__ out) {
    __shared__ float scos[32];
    __shared__ float sgate[32];
    __shared__ __align__(16) ull hb2[64 * HH];   // hbar duplicated {v,v}, [row][h]
    int r0 = blockIdx.y * 64;
    int t = threadIdx.x;
    if (t < 32) {
        // cos from cred partials
        float D = 0.f, A = 0.f, E = 0.f;
#pragma unroll 8
        for (int c = 0; c < 32; c++) {
            float4 f = g_cred[t * 32 + c];
            D += f.x; A += f.y; E += f.z;
        }
        scos[t] = D / fmaxf(sqrtf(E) * sqrtf(A), COSEPS);   // scos[p*BB+b]
        __syncwarp();
        // double softmax over p for batch bq = t>>3; store gate for p = t&7
        int bq = t >> 3, p = t & 7;
        float x[PP], m = -1e30f;
#pragma unroll
        for (int pp = 0; pp < PP; pp++) { x[pp] = scos[pp * BB + bq]; m = fmaxf(m, x[pp]); }
        float z = 0.f;
#pragma unroll
        for (int pp = 0; pp < PP; pp++) { x[pp] = expf(x[pp] - m); z += x[pp]; }
#pragma unroll
        for (int pp = 0; pp < PP; pp++) x[pp] /= z;        // s_t
        m = -1e30f;
#pragma unroll
        for (int pp = 0; pp < PP; pp++) m = fmaxf(m, x[pp]);
        z = 0.f;
#pragma unroll
        for (int pp = 0; pp < PP; pp++) { x[pp] = expf(x[pp] - m); z += x[pp]; }
        sgate[t] = x[p] / z;                                // gate[bq][p]
    }
    __syncthreads();
    for (int i = t; i < 64 * HH; i += 128) {
        int r = i / HH, h = i - r * HH;
        int bv = r0 + r;
        int pf = prefix[bv];
        int bq = bv >> 6;
        float s = 0.f;
#pragma unroll
        for (int p = 0; p < PP; p++)
            s += sgate[bq * 8 + p] * g_htab[((size_t)p * VV + pf) * HH + h];
        hb2[i] = pack2(s, s);
    }
    __syncthreads();
    int kp = blockIdx.x * 256 + t * 2;
    ull wcol[HH];
#pragma unroll
    for (int h = 0; h < HH; h++) {
        float2 wv = *reinterpret_cast<const float2*>(w2 + (size_t)h * KK + kp);
        wcol[h] = pack2(wv.x, wv.y);
    }
    float2 bv2 = *reinterpret_cast<const float2*>(b2 + kp);
    ull binit = pack2(bv2.x, bv2.y);
    for (int rg = 0; rg < 64; rg += 4) {
        ull a0 = binit, a1 = binit, a2 = binit, a3 = binit;
#pragma unroll
        for (int hp = 0; hp < HH / 2; hp++) {
            // LDS.128: two h-values per smem load, each feeds 2 FFMA2
            ulonglong2 h0 = *reinterpret_cast<const ulonglong2*>(&hb2[(rg + 0) * HH + 2 * hp]);
            ulonglong2 h1 = *reinterpret_cast<const ulonglong2*>(&hb2[(rg + 1) * HH + 2 * hp]);
            ulonglong2 h2 = *reinterpret_cast<const ulonglong2*>(&hb2[(rg + 2) * HH + 2 * hp]);
            ulonglong2 h3 = *reinterpret_cast<const ulonglong2*>(&hb2[(rg + 3) * HH + 2 * hp]);
            ull w0 = wcol[2 * hp], w1v = wcol[2 * hp + 1];
            a0 = fma2(w0, h0.x, a0); a0 = fma2(w1v, h0.y, a0);
            a1 = fma2(w0, h1.x, a1); a1 = fma2(w1v, h1.y, a1);
            a2 = fma2(w0, h2.x, a2); a2 = fma2(w1v, h2.y, a2);
            a3 = fma2(w0, h3.x, a3); a3 = fma2(w1v, h3.y, a3);
        }
        *reinterpret_cast<float2*>(out + (size_t)(r0 + rg + 0) * KK + kp) = unpack2(a0);
        *reinterpret_cast<float2*>(out + (size_t)(r0 + rg + 1) * KK + kp) = unpack2(a1);
        *reinterpret_cast<float2*>(out + (size_t)(r0 + rg + 2) * KK + kp) = unpack2(a2);
        *reinterpret_cast<float2*>(out + (size_t)(r0 + rg + 3) * KK + kp) = unpack2(a3);
    }
}

// ---------------- launcher ----------------
extern "C" void kernel_launch(void* const* d_in, const int* in_sizes, int n_in,
                              void* d_out, int out_size) {
    const int* prefix = nullptr;
    const float *ctx = nullptr, *tables = nullptr, *lora = nullptr;
    const float *w1 = nullptr, *b1 = nullptr, *w2 = nullptr, *b2 = nullptr;
    for (int i = 0; i < n_in; i++) {
        switch (in_sizes[i]) {
            case 256:     prefix = (const int*)d_in[i];   break;  // (B,V) int32
            case 8388608: ctx    = (const float*)d_in[i]; break;  // (B,S,D)
            case 524288:  tables = (const float*)d_in[i]; break;  // (P,V,D)
            case 8192:    lora   = (const float*)d_in[i]; break;  // (P,D)
            case 43008:   w1     = (const float*)d_in[i]; break;  // (D,H)
            case 42:      b1     = (const float*)d_in[i]; break;  // (H,)
            case 2064384: w2     = (const float*)d_in[i]; break;  // (H,K)
            case 49152:   b2     = (const float*)d_in[i]; break;  // (K,)
        }
    }
    float* out = (float*)d_out;

    const int kavd_smem = (PP * SS + 32 * PP * 32) * 4;   // 98304 B
    cudaFuncSetAttribute(kavd, cudaFuncAttributeMaxDynamicSharedMemorySize, kavd_smem);

    knorm<<<1024, 256>>>(ctx, lora, w1);
    ksofth<<<96, 256>>>(tables, b1);
    kavd<<<128, 1024, kavd_smem>>>(ctx, lora);
    kout<<<dim3(192, 4), 128>>>(prefix, w2, b2, out);   // 4th launch -> profiled
}